// round 11
// baseline (speedup 1.0000x reference)
#include <cuda_runtime.h>
#include <cuda_bf16.h>
#include <mma.h>
#include <cstdint>

using namespace nvcuda;
typedef __nv_bfloat16 bf16;
typedef unsigned int uint;

__device__ __forceinline__ float sigmoidf(float x) {
    return __fdividef(1.0f, 1.0f + __expf(-x));
}
// bf16 hi/lo split: v = h + l + O(2^-18 v)
__device__ __forceinline__ void bsplit(float v, bf16& h, bf16& l) {
    h = __float2bfloat16(v);
    l = __float2bfloat16(v - __bfloat162float(h));
}

typedef wmma::fragment<wmma::accumulator, 16, 16, 16, float> FragC;
typedef wmma::fragment<wmma::matrix_a, 16, 16, 16, bf16, wmma::row_major> FragA;

// 3-term split mma: C += Ah*Bh + Ah*Bl + Al*Bh
template <typename BL>
__device__ __forceinline__ void mma3(FragC& c, const FragA& ah, const FragA& al,
                                     const bf16* bh_p, const bf16* bl_p) {
    wmma::fragment<wmma::matrix_b, 16, 16, 16, bf16, BL> bh, bl;
    wmma::load_matrix_sync(bh, bh_p, 72);
    wmma::load_matrix_sync(bl, bl_p, 72);
    wmma::mma_sync(c, ah, bh, c);
    wmma::mma_sync(c, ah, bl, c);
    wmma::mma_sync(c, al, bh, c);
}

// Warp-local: store 16x16 fp32 frag -> scratch, split to bf16 hi/lo region
// (dh/dl are the 16x16 region bases with row stride 72).
__device__ __forceinline__ void conv_frag(float* scr, const FragC& cf,
                                          bf16* dh, bf16* dl, int lane) {
    wmma::store_matrix_sync(scr, cf, 20, wmma::mem_row_major);
    __syncwarp();
#pragma unroll
    for (int e = 0; e < 8; e += 2) {
        int idx = lane * 8 + e;
        int row = idx >> 4, col = idx & 15;
        float v0 = scr[row * 20 + col], v1 = scr[row * 20 + col + 1];
        bf16 h0, l0, h1, l1;
        bsplit(v0, h0, l0); bsplit(v1, h1, l1);
        *(__nv_bfloat162*)(dh + row * 72 + col) = __nv_bfloat162(h0, h1);
        *(__nv_bfloat162*)(dl + row * 72 + col) = __nv_bfloat162(l0, l1);
    }
    __syncwarp();
}

// xg scratch: [l][g][n][a][b]  (384 MB device .bss)
__device__ float g_xg[(size_t)3 * 128 * 64 * 64 * 64];

// ============================================================================
// Phase 1 (wmma, gates parallel): per (l,n) tile:
//   stage A: T_g[i,b] = sum_j X[i,j] W2[g,b,j]   12 warps = (g, mt)
//   stage B: xg_g[a,b] = sum_i W1[g,a,i] T_g[i,b] -> global store_matrix
// ============================================================================
#define XG_XH   0
#define XG_XL   18432
#define XG_W2H  36864
#define XG_W2L  64512
#define XG_W1H  92160
#define XG_W1L  119808
#define XG_TH   147456
#define XG_TL   175104
#define XG_SCR  202752      // 12 warps x 16x20 fp32 (1280 B each)
#define XG_SMEM 218112

// element layouts: XH/XL [64][72]; W*/T* [3][64][72]; all bf16
__global__ void __launch_bounds__(384, 1)
xg_kernel(const float* __restrict__ inputs,
          const float* __restrict__ Ww1,
          const float* __restrict__ Ww2) {
    extern __shared__ char smx[];
    bf16* XH  = (bf16*)(smx + XG_XH);
    bf16* XL  = (bf16*)(smx + XG_XL);
    bf16* W2H = (bf16*)(smx + XG_W2H);
    bf16* W2L = (bf16*)(smx + XG_W2L);
    bf16* W1H = (bf16*)(smx + XG_W1H);
    bf16* W1L = (bf16*)(smx + XG_W1L);
    bf16* TH  = (bf16*)(smx + XG_TH);
    bf16* TL  = (bf16*)(smx + XG_TL);

    const int tid = threadIdx.x;
    const int w = tid >> 5, lane = tid & 31;
    const int g = w >> 2, mt = w & 3;
    float* scr = (float*)(smx + XG_SCR) + w * 320;

    // one-time weight staging
    for (int e = tid; e < 12288; e += 384) {
        int gg = e >> 12, r = (e >> 6) & 63, c = e & 63;
        bf16 h, l;
        bsplit(Ww2[e], h, l);
        W2H[gg * 4608 + r * 72 + c] = h;
        W2L[gg * 4608 + r * 72 + c] = l;
        bsplit(Ww1[e], h, l);
        W1H[gg * 4608 + r * 72 + c] = h;
        W1L[gg * 4608 + r * 72 + c] = l;
    }
    __syncthreads();

    for (int t = 0; t < 8; ++t) {
        const int flat = blockIdx.x * 8 + t;
        const int l = flat >> 6, n = flat & 63;

        const float* xsrc = inputs + ((size_t)n * 128 + l) * 4096;
        for (int e = tid; e < 4096; e += 384) {
            int i = e >> 6, j = e & 63;
            bf16 h, lo; bsplit(xsrc[e], h, lo);
            XH[i * 72 + j] = h;
            XL[i * 72 + j] = lo;
        }
        __syncthreads();

        // ---- stage A: warp (g, mt) -> T_g rows 16mt, all 64 cols ----
        {
            FragC c[4];
#pragma unroll
            for (int nt = 0; nt < 4; ++nt) wmma::fill_fragment(c[nt], 0.0f);
#pragma unroll
            for (int k = 0; k < 4; ++k) {
                FragA ah, al;
                wmma::load_matrix_sync(ah, XH + mt * 16 * 72 + k * 16, 72);
                wmma::load_matrix_sync(al, XL + mt * 16 * 72 + k * 16, 72);
#pragma unroll
                for (int nt = 0; nt < 4; ++nt)
                    mma3<wmma::col_major>(c[nt], ah, al,
                        W2H + g * 4608 + nt * 16 * 72 + k * 16,
                        W2L + g * 4608 + nt * 16 * 72 + k * 16);
            }
#pragma unroll
            for (int nt = 0; nt < 4; ++nt)
                conv_frag(scr, c[nt],
                          TH + g * 4608 + mt * 16 * 72 + nt * 16,
                          TL + g * 4608 + mt * 16 * 72 + nt * 16, lane);
        }
        __syncthreads();

        // ---- stage B: warp (g, mt) -> xg_g rows 16mt -> global ----
        {
            FragC c[4];
#pragma unroll
            for (int nt = 0; nt < 4; ++nt) wmma::fill_fragment(c[nt], 0.0f);
#pragma unroll
            for (int k = 0; k < 4; ++k) {
                FragA ah, al;
                wmma::load_matrix_sync(ah, W1H + g * 4608 + mt * 16 * 72 + k * 16, 72);
                wmma::load_matrix_sync(al, W1L + g * 4608 + mt * 16 * 72 + k * 16, 72);
#pragma unroll
                for (int nt = 0; nt < 4; ++nt)
                    mma3<wmma::row_major>(c[nt], ah, al,
                        TH + g * 4608 + k * 16 * 72 + nt * 16,
                        TL + g * 4608 + k * 16 * 72 + nt * 16);
            }
            float* dst = g_xg + ((size_t)(l * 3 + g) * 64 + n) * 4096 + mt * 16 * 64;
#pragma unroll
            for (int nt = 0; nt < 4; ++nt)
                wmma::store_matrix_sync(dst + nt * 16, c[nt], 64, wmma::mem_row_major);
        }
        __syncthreads();   // X/TH reuse next tile
    }
}

// ============================================================================
// Phase 2 (wmma, 2 syncs/step): one CTA per n.
//  stage1 (12 warps, (g,mt)): tmp_g[a,j] = sum_i W1[g,a,i] h[i,j] -> split TH/TL
//  stage2 (8 warps, (mt,nh)): for all 3 gates, hg[a,b] 16x32 region in frags,
//          then warp-local elementwise (c-state in registers), h -> smem+out.
// ============================================================================
#define RC_HH   0
#define RC_HL   9216
#define RC_W1H  18432
#define RC_W1L  46080
#define RC_W2H  73728
#define RC_W2L  101376
#define RC_TH   129024
#define RC_TL   156672
#define RC_SCR  184320      // 8 warps x 3 x 16x20 fp32 (3840 B each)
#define RC_SMEM 215040

__global__ void __launch_bounds__(384, 1)
rec_kernel(const float* __restrict__ Wu1,
           const float* __restrict__ Wu2,
           float* __restrict__ out) {
    extern __shared__ char smx[];
    bf16* HH  = (bf16*)(smx + RC_HH);    // [64][72]
    bf16* HL  = (bf16*)(smx + RC_HL);
    bf16* W1H = (bf16*)(smx + RC_W1H);   // [3][64][72]
    bf16* W1L = (bf16*)(smx + RC_W1L);
    bf16* W2H = (bf16*)(smx + RC_W2H);
    bf16* W2L = (bf16*)(smx + RC_W2L);
    bf16* TH  = (bf16*)(smx + RC_TH);
    bf16* TL  = (bf16*)(smx + RC_TL);

    const int n = blockIdx.x;
    const int tid = threadIdx.x;
    const int w = tid >> 5, lane = tid & 31;
    const int g1 = w >> 2, mt1 = w & 3;       // stage1 role
    const int mt2 = w >> 1, nh2 = w & 1;      // stage2 role (w < 8)
    float* scr1 = (float*)(smx + RC_SCR) + w * 320;          // stage1 conv scratch
    float* scr2 = (float*)(smx + RC_SCR) + w * 960;          // stage2 elemwise (w<8)

    for (int e = tid; e < 12288; e += 384) {
        int gg = e >> 12, r = (e >> 6) & 63, c = e & 63;
        bf16 h, l;
        bsplit(Wu1[e], h, l);
        W1H[gg * 4608 + r * 72 + c] = h;
        W1L[gg * 4608 + r * 72 + c] = l;
        bsplit(Wu2[e], h, l);
        W2H[gg * 4608 + r * 72 + c] = h;
        W2L[gg * 4608 + r * 72 + c] = l;
    }
    for (int e = tid; e < 4608; e += 384) {
        HH[e] = __float2bfloat16(0.f);
        HL[e] = __float2bfloat16(0.f);
    }
    float cst[16];
#pragma unroll
    for (int e = 0; e < 16; ++e) cst[e] = 0.f;
    __syncthreads();

    for (int l = 0; l < 128; ++l) {
        // ---- stage1: warp (g1, mt1): tmp rows 16*mt1, cols 0..63 ----
        {
            FragC c[4];
#pragma unroll
            for (int nt = 0; nt < 4; ++nt) wmma::fill_fragment(c[nt], 0.0f);
#pragma unroll
            for (int k = 0; k < 4; ++k) {
                FragA ah, al;
                wmma::load_matrix_sync(ah, W1H + g1 * 4608 + mt1 * 16 * 72 + k * 16, 72);
                wmma::load_matrix_sync(al, W1L + g1 * 4608 + mt1 * 16 * 72 + k * 16, 72);
#pragma unroll
                for (int nt = 0; nt < 4; ++nt)
                    mma3<wmma::row_major>(c[nt], ah, al,
                        HH + k * 16 * 72 + nt * 16,
                        HL + k * 16 * 72 + nt * 16);
            }
#pragma unroll
            for (int nt = 0; nt < 4; ++nt)
                conv_frag(scr1, c[nt],
                          TH + g1 * 4608 + mt1 * 16 * 72 + nt * 16,
                          TL + g1 * 4608 + mt1 * 16 * 72 + nt * 16, lane);
        }
        __syncthreads();

        // ---- stage2 + elementwise: warps 0..7, region rows 16*mt2 cols 32*nh2 ----
        if (w < 8) {
            FragC c[3][2];
#pragma unroll
            for (int gg = 0; gg < 3; ++gg)
#pragma unroll
                for (int nt = 0; nt < 2; ++nt) wmma::fill_fragment(c[gg][nt], 0.0f);
#pragma unroll
            for (int gg = 0; gg < 3; ++gg) {
#pragma unroll
                for (int k = 0; k < 4; ++k) {
                    FragA ah, al;
                    wmma::load_matrix_sync(ah, TH + gg * 4608 + mt2 * 16 * 72 + k * 16, 72);
                    wmma::load_matrix_sync(al, TL + gg * 4608 + mt2 * 16 * 72 + k * 16, 72);
#pragma unroll
                    for (int nt = 0; nt < 2; ++nt) {
                        int ntg = nh2 * 2 + nt;
                        mma3<wmma::col_major>(c[gg][nt], ah, al,
                            W2H + gg * 4608 + ntg * 16 * 72 + k * 16,
                            W2L + gg * 4608 + ntg * 16 * 72 + k * 16);
                    }
                }
            }
            // warp-local elementwise, per 16x16 subtile
#pragma unroll
            for (int nt = 0; nt < 2; ++nt) {
                wmma::store_matrix_sync(scr2,       c[0][nt], 20, wmma::mem_row_major);
                wmma::store_matrix_sync(scr2 + 320, c[1][nt], 20, wmma::mem_row_major);
                wmma::store_matrix_sync(scr2 + 640, c[2][nt], 20, wmma::mem_row_major);
                __syncwarp();
                const size_t xgbase = ((size_t)(l * 3) * 64 + n) * 4096;
                float* orow = out + ((size_t)n * 128 + l) * 4096;
#pragma unroll
                for (int e = 0; e < 8; ++e) {
                    int idx = lane * 8 + e;
                    int row = idx >> 4, col = idx & 15;
                    int a = mt2 * 16 + row, b = (nh2 * 2 + nt) * 16 + col;
                    float z = sigmoidf(scr2[row * 20 + col] +
                                       g_xg[xgbase + (size_t)a * 64 + b]);
                    float r = sigmoidf(scr2[320 + row * 20 + col] +
                                       g_xg[xgbase + 262144 + (size_t)a * 64 + b]);
                    float o = sigmoidf(scr2[640 + row * 20 + col] +
                                       g_xg[xgbase + 524288 + (size_t)a * 64 + b]);
                    int ci = nt * 8 + e;
                    float cn = r * (cst[ci] + z);   // c = r*c + z*r
                    cst[ci] = cn;
                    float hv = o * sigmoidf(cn);    // h = o*sig(c)
                    orow[a * 64 + b] = hv;
                    bf16 hh, hl;
                    bsplit(hv, hh, hl);
                    HH[a * 72 + b] = hh;
                    HL[a * 72 + b] = hl;
                }
                __syncwarp();
            }
        }
        __syncthreads();   // h complete before next stage1
    }

    // epilogue: h_last = outs[:,127] copy; c_last from stage2 registers
    {
        const float* hsrc = out + ((size_t)n * 128 + 127) * 4096;
        float* hl = out + 33554432ull + (size_t)n * 4096;
        for (int e = tid; e < 4096; e += 384) hl[e] = hsrc[e];
        if (w < 8) {
            float* cl = out + 33816576ull + (size_t)n * 4096;
#pragma unroll
            for (int nt = 0; nt < 2; ++nt)
#pragma unroll
                for (int e = 0; e < 8; ++e) {
                    int idx = lane * 8 + e;
                    int a = mt2 * 16 + (idx >> 4);
                    int b = (nh2 * 2 + nt) * 16 + (idx & 15);
                    cl[a * 64 + b] = cst[nt * 8 + e];
                }
        }
    }
}

// ============================================================================
extern "C" void kernel_launch(void* const* d_in, const int* in_sizes, int n_in,
                              void* d_out, int out_size) {
    const float* inputs = (const float*)d_in[0];   // (64,128,64,64)
    const float* Ww1    = (const float*)d_in[1];   // (4,64,64) — g<3 used
    const float* Ww2    = (const float*)d_in[2];
    const float* Wu1    = (const float*)d_in[3];
    const float* Wu2    = (const float*)d_in[4];
    float* out = (float*)d_out;

    cudaFuncSetAttribute(xg_kernel,  cudaFuncAttributeMaxDynamicSharedMemorySize, XG_SMEM);
    cudaFuncSetAttribute(rec_kernel, cudaFuncAttributeMaxDynamicSharedMemorySize, RC_SMEM);

    xg_kernel<<<1024, 384, XG_SMEM>>>(inputs, Ww1, Ww2);
    rec_kernel<<<64, 384, RC_SMEM>>>(Wu1, Wu2, out);
}

// round 12
// speedup vs baseline: 1.5547x; 1.5547x over previous
#include <cuda_runtime.h>
#include <cuda_bf16.h>
#include <mma.h>
#include <cstdint>

using namespace nvcuda;
typedef __nv_bfloat16 bf16;
typedef unsigned int uint;

__device__ __forceinline__ float sigmoidf(float x) {
    return __fdividef(1.0f, 1.0f + __expf(-x));
}
// bf16 hi/lo split: v = h + l + O(2^-18 v)
__device__ __forceinline__ void bsplit(float v, bf16& h, bf16& l) {
    h = __float2bfloat16(v);
    l = __float2bfloat16(v - __bfloat162float(h));
}

typedef wmma::fragment<wmma::accumulator, 16, 16, 16, float> FragC;
typedef wmma::fragment<wmma::matrix_a, 16, 16, 16, bf16, wmma::row_major> FragA;

// 3-term split mma: C += Ah*Bh + Ah*Bl + Al*Bh
template <typename BL>
__device__ __forceinline__ void mma3(FragC& c, const FragA& ah, const FragA& al,
                                     const bf16* bh_p, const bf16* bl_p) {
    wmma::fragment<wmma::matrix_b, 16, 16, 16, bf16, BL> bh, bl;
    wmma::load_matrix_sync(bh, bh_p, 72);
    wmma::load_matrix_sync(bl, bl_p, 72);
    wmma::mma_sync(c, ah, bh, c);
    wmma::mma_sync(c, ah, bl, c);
    wmma::mma_sync(c, al, bh, c);
}

// Warp-local: store 16x16 fp32 frag -> scratch, split to bf16 hi/lo region
__device__ __forceinline__ void conv_frag(float* scr, const FragC& cf,
                                          bf16* dh, bf16* dl, int lane) {
    wmma::store_matrix_sync(scr, cf, 20, wmma::mem_row_major);
    __syncwarp();
#pragma unroll
    for (int e = 0; e < 8; e += 2) {
        int idx = lane * 8 + e;
        int row = idx >> 4, col = idx & 15;
        float v0 = scr[row * 20 + col], v1 = scr[row * 20 + col + 1];
        bf16 h0, l0, h1, l1;
        bsplit(v0, h0, l0); bsplit(v1, h1, l1);
        *(__nv_bfloat162*)(dh + row * 72 + col) = __nv_bfloat162(h0, h1);
        *(__nv_bfloat162*)(dl + row * 72 + col) = __nv_bfloat162(l0, l1);
    }
    __syncwarp();
}

// xg scratch: [l][g][n][a][b]  (384 MB device .bss)
__device__ float g_xg[(size_t)3 * 128 * 64 * 64 * 64];

// ============================================================================
// Phase 1 (unchanged R10 — validated): gates-parallel wmma.
// ============================================================================
#define XG_XH   0
#define XG_XL   18432
#define XG_W2H  36864
#define XG_W2L  64512
#define XG_W1H  92160
#define XG_W1L  119808
#define XG_TH   147456
#define XG_TL   175104
#define XG_SCR  202752
#define XG_SMEM 218112

__global__ void __launch_bounds__(384, 1)
xg_kernel(const float* __restrict__ inputs,
          const float* __restrict__ Ww1,
          const float* __restrict__ Ww2) {
    extern __shared__ char smx[];
    bf16* XH  = (bf16*)(smx + XG_XH);
    bf16* XL  = (bf16*)(smx + XG_XL);
    bf16* W2H = (bf16*)(smx + XG_W2H);
    bf16* W2L = (bf16*)(smx + XG_W2L);
    bf16* W1H = (bf16*)(smx + XG_W1H);
    bf16* W1L = (bf16*)(smx + XG_W1L);
    bf16* TH  = (bf16*)(smx + XG_TH);
    bf16* TL  = (bf16*)(smx + XG_TL);

    const int tid = threadIdx.x;
    const int w = tid >> 5, lane = tid & 31;
    const int g = w >> 2, mt = w & 3;
    float* scr = (float*)(smx + XG_SCR) + w * 320;

    for (int e = tid; e < 12288; e += 384) {
        int gg = e >> 12, r = (e >> 6) & 63, c = e & 63;
        bf16 h, l;
        bsplit(Ww2[e], h, l);
        W2H[gg * 4608 + r * 72 + c] = h;
        W2L[gg * 4608 + r * 72 + c] = l;
        bsplit(Ww1[e], h, l);
        W1H[gg * 4608 + r * 72 + c] = h;
        W1L[gg * 4608 + r * 72 + c] = l;
    }
    __syncthreads();

    for (int t = 0; t < 8; ++t) {
        const int flat = blockIdx.x * 8 + t;
        const int l = flat >> 6, n = flat & 63;

        const float* xsrc = inputs + ((size_t)n * 128 + l) * 4096;
        for (int e = tid; e < 4096; e += 384) {
            int i = e >> 6, j = e & 63;
            bf16 h, lo; bsplit(xsrc[e], h, lo);
            XH[i * 72 + j] = h;
            XL[i * 72 + j] = lo;
        }
        __syncthreads();

        {   // stage A
            FragC c[4];
#pragma unroll
            for (int nt = 0; nt < 4; ++nt) wmma::fill_fragment(c[nt], 0.0f);
#pragma unroll
            for (int k = 0; k < 4; ++k) {
                FragA ah, al;
                wmma::load_matrix_sync(ah, XH + mt * 16 * 72 + k * 16, 72);
                wmma::load_matrix_sync(al, XL + mt * 16 * 72 + k * 16, 72);
#pragma unroll
                for (int nt = 0; nt < 4; ++nt)
                    mma3<wmma::col_major>(c[nt], ah, al,
                        W2H + g * 4608 + nt * 16 * 72 + k * 16,
                        W2L + g * 4608 + nt * 16 * 72 + k * 16);
            }
#pragma unroll
            for (int nt = 0; nt < 4; ++nt)
                conv_frag(scr, c[nt],
                          TH + g * 4608 + mt * 16 * 72 + nt * 16,
                          TL + g * 4608 + mt * 16 * 72 + nt * 16, lane);
        }
        __syncthreads();

        {   // stage B -> global
            FragC c[4];
#pragma unroll
            for (int nt = 0; nt < 4; ++nt) wmma::fill_fragment(c[nt], 0.0f);
#pragma unroll
            for (int k = 0; k < 4; ++k) {
                FragA ah, al;
                wmma::load_matrix_sync(ah, W1H + g * 4608 + mt * 16 * 72 + k * 16, 72);
                wmma::load_matrix_sync(al, W1L + g * 4608 + mt * 16 * 72 + k * 16, 72);
#pragma unroll
                for (int nt = 0; nt < 4; ++nt)
                    mma3<wmma::row_major>(c[nt], ah, al,
                        TH + g * 4608 + k * 16 * 72 + nt * 16,
                        TL + g * 4608 + k * 16 * 72 + nt * 16);
            }
            float* dst = g_xg + ((size_t)(l * 3 + g) * 64 + n) * 4096 + mt * 16 * 64;
#pragma unroll
            for (int nt = 0; nt < 4; ++nt)
                wmma::store_matrix_sync(dst + nt * 16, c[nt], 64, wmma::mem_row_major);
        }
        __syncthreads();
    }
}

// ============================================================================
// Phase 2: wmma, 2 syncs/step. Stage2 accumulators INITIALIZED from g_xg
// (fragment global loads, latency overlapped); elementwise directly on
// fragment elements (c-state cst[i] <-> x[i], layout identical across frags).
// ============================================================================
#define RC_HH   0
#define RC_HL   9216
#define RC_W1H  18432
#define RC_W1L  46080
#define RC_W2H  73728
#define RC_W2L  101376
#define RC_TH   129024
#define RC_TL   156672
#define RC_SCR  184320      // 12 warps x 320 fp32
#define RC_SMEM 199680

__global__ void __launch_bounds__(384, 1)
rec_kernel(const float* __restrict__ Wu1,
           const float* __restrict__ Wu2,
           float* __restrict__ out) {
    extern __shared__ char smx[];
    bf16* HH  = (bf16*)(smx + RC_HH);
    bf16* HL  = (bf16*)(smx + RC_HL);
    bf16* W1H = (bf16*)(smx + RC_W1H);
    bf16* W1L = (bf16*)(smx + RC_W1L);
    bf16* W2H = (bf16*)(smx + RC_W2H);
    bf16* W2L = (bf16*)(smx + RC_W2L);
    bf16* TH  = (bf16*)(smx + RC_TH);
    bf16* TL  = (bf16*)(smx + RC_TL);

    const int n = blockIdx.x;
    const int tid = threadIdx.x;
    const int w = tid >> 5, lane = tid & 31;
    const int g1 = w >> 2, mt1 = w & 3;
    const int mt2 = w >> 1, nh2 = w & 1;
    float* scrw = (float*)(smx + RC_SCR) + w * 320;

    for (int e = tid; e < 12288; e += 384) {
        int gg = e >> 12, r = (e >> 6) & 63, c = e & 63;
        bf16 h, l;
        bsplit(Wu1[e], h, l);
        W1H[gg * 4608 + r * 72 + c] = h;
        W1L[gg * 4608 + r * 72 + c] = l;
        bsplit(Wu2[e], h, l);
        W2H[gg * 4608 + r * 72 + c] = h;
        W2L[gg * 4608 + r * 72 + c] = l;
    }
    for (int e = tid; e < 4608; e += 384) {
        HH[e] = __float2bfloat16(0.f);
        HL[e] = __float2bfloat16(0.f);
    }
    float cst[16];
#pragma unroll
    for (int e = 0; e < 16; ++e) cst[e] = 0.f;
    __syncthreads();

    for (int l = 0; l < 128; ++l) {
        // ---- stage1: 12 warps (g1, mt1): tmp -> TH/TL ----
        {
            FragC c1[4];
#pragma unroll
            for (int nt = 0; nt < 4; ++nt) wmma::fill_fragment(c1[nt], 0.0f);
#pragma unroll
            for (int k = 0; k < 4; ++k) {
                FragA ah, al;
                wmma::load_matrix_sync(ah, W1H + g1 * 4608 + mt1 * 16 * 72 + k * 16, 72);
                wmma::load_matrix_sync(al, W1L + g1 * 4608 + mt1 * 16 * 72 + k * 16, 72);
#pragma unroll
                for (int nt = 0; nt < 4; ++nt)
                    mma3<wmma::row_major>(c1[nt], ah, al,
                        HH + k * 16 * 72 + nt * 16,
                        HL + k * 16 * 72 + nt * 16);
            }
#pragma unroll
            for (int nt = 0; nt < 4; ++nt)
                conv_frag(scrw, c1[nt],
                          TH + g1 * 4608 + mt1 * 16 * 72 + nt * 16,
                          TL + g1 * 4608 + mt1 * 16 * 72 + nt * 16, lane);
        }
        __syncthreads();

        // ---- stage2 + elementwise: warps 0..7, region rows 16*mt2 cols 32*nh2 ----
        if (w < 8) {
            FragC c[3][2];
            // accumulators start as xg (global fragment loads; latency
            // overlapped by the mma issue stream below)
#pragma unroll
            for (int gg = 0; gg < 3; ++gg)
#pragma unroll
                for (int nt = 0; nt < 2; ++nt)
                    wmma::load_matrix_sync(c[gg][nt],
                        g_xg + ((size_t)(l * 3 + gg) * 64 + n) * 4096
                             + (mt2 * 16) * 64 + (nh2 * 2 + nt) * 16,
                        64, wmma::mem_row_major);
#pragma unroll
            for (int gg = 0; gg < 3; ++gg) {
#pragma unroll
                for (int k = 0; k < 4; ++k) {
                    FragA ah, al;
                    wmma::load_matrix_sync(ah, TH + gg * 4608 + mt2 * 16 * 72 + k * 16, 72);
                    wmma::load_matrix_sync(al, TL + gg * 4608 + mt2 * 16 * 72 + k * 16, 72);
#pragma unroll
                    for (int nt = 0; nt < 2; ++nt) {
                        int ntg = nh2 * 2 + nt;
                        mma3<wmma::col_major>(c[gg][nt], ah, al,
                            W2H + gg * 4608 + ntg * 16 * 72 + k * 16,
                            W2L + gg * 4608 + ntg * 16 * 72 + k * 16);
                    }
                }
            }
            // elementwise in registers (identical accumulator layouts)
            float* orow = out + ((size_t)n * 128 + l) * 4096;
#pragma unroll
            for (int nt = 0; nt < 2; ++nt) {
#pragma unroll
                for (int i = 0; i < 8; ++i) {
                    float z = sigmoidf(c[0][nt].x[i]);
                    float r = sigmoidf(c[1][nt].x[i]);
                    float o = sigmoidf(c[2][nt].x[i]);
                    int ci = nt * 8 + i;
                    float cn = r * (cst[ci] + z);   // c = r*c + z*r
                    cst[ci] = cn;
                    c[0][nt].x[i] = o * sigmoidf(cn);  // h
                }
                wmma::store_matrix_sync(scrw, c[0][nt], 20, wmma::mem_row_major);
                __syncwarp();
#pragma unroll
                for (int e = 0; e < 8; e += 2) {
                    int idx = lane * 8 + e;
                    int row = idx >> 4, col = idx & 15;
                    int a = mt2 * 16 + row, b = (nh2 * 2 + nt) * 16 + col;
                    float v0 = scrw[row * 20 + col], v1 = scrw[row * 20 + col + 1];
                    *(float2*)(orow + a * 64 + b) = make_float2(v0, v1);
                    bf16 h0, l0, h1, l1;
                    bsplit(v0, h0, l0); bsplit(v1, h1, l1);
                    *(__nv_bfloat162*)(HH + a * 72 + b) = __nv_bfloat162(h0, h1);
                    *(__nv_bfloat162*)(HL + a * 72 + b) = __nv_bfloat162(l0, l1);
                }
                __syncwarp();
            }
        }
        __syncthreads();
    }

    // epilogue: h_last = outs[:,127]; c_last via fragment->scratch for coords
    {
        const float* hsrc = out + ((size_t)n * 128 + 127) * 4096;
        float* hl = out + 33554432ull + (size_t)n * 4096;
        for (int e = tid; e < 4096; e += 384) hl[e] = hsrc[e];
        if (w < 8) {
            float* cl = out + 33816576ull + (size_t)n * 4096;
#pragma unroll
            for (int nt = 0; nt < 2; ++nt) {
                FragC cf;
#pragma unroll
                for (int i = 0; i < 8; ++i) cf.x[i] = cst[nt * 8 + i];
                wmma::store_matrix_sync(scrw, cf, 20, wmma::mem_row_major);
                __syncwarp();
#pragma unroll
                for (int e = 0; e < 8; e += 2) {
                    int idx = lane * 8 + e;
                    int row = idx >> 4, col = idx & 15;
                    int a = mt2 * 16 + row, b = (nh2 * 2 + nt) * 16 + col;
                    *(float2*)(cl + a * 64 + b) =
                        make_float2(scrw[row * 20 + col], scrw[row * 20 + col + 1]);
                }
                __syncwarp();
            }
        }
    }
}

// ============================================================================
extern "C" void kernel_launch(void* const* d_in, const int* in_sizes, int n_in,
                              void* d_out, int out_size) {
    const float* inputs = (const float*)d_in[0];   // (64,128,64,64)
    const float* Ww1    = (const float*)d_in[1];   // (4,64,64) — g<3 used
    const float* Ww2    = (const float*)d_in[2];
    const float* Wu1    = (const float*)d_in[3];
    const float* Wu2    = (const float*)d_in[4];
    float* out = (float*)d_out;

    cudaFuncSetAttribute(xg_kernel,  cudaFuncAttributeMaxDynamicSharedMemorySize, XG_SMEM);
    cudaFuncSetAttribute(rec_kernel, cudaFuncAttributeMaxDynamicSharedMemorySize, RC_SMEM);

    xg_kernel<<<1024, 384, XG_SMEM>>>(inputs, Ww1, Ww2);
    rec_kernel<<<64, 384, RC_SMEM>>>(Wu1, Wu2, out);
}

// round 13
// speedup vs baseline: 1.7494x; 1.1252x over previous
#include <cuda_runtime.h>
#include <cuda_bf16.h>
#include <mma.h>
#include <cstdint>

using namespace nvcuda;
typedef __nv_bfloat16 bf16;
typedef unsigned int uint;

__device__ __forceinline__ float sigmoidf(float x) {
    return __fdividef(1.0f, 1.0f + __expf(-x));
}
// bf16 hi/lo split: v = h + l + O(2^-18 v)
__device__ __forceinline__ void bsplit(float v, bf16& h, bf16& l) {
    h = __float2bfloat16(v);
    l = __float2bfloat16(v - __bfloat162float(h));
}

typedef wmma::fragment<wmma::accumulator, 16, 16, 16, float> FragC;
typedef wmma::fragment<wmma::matrix_a, 16, 16, 16, bf16, wmma::row_major> FragA;

// 3-term split mma: C += Ah*Bh + Ah*Bl + Al*Bh
template <typename BL>
__device__ __forceinline__ void mma3(FragC& c, const FragA& ah, const FragA& al,
                                     const bf16* bh_p, const bf16* bl_p) {
    wmma::fragment<wmma::matrix_b, 16, 16, 16, bf16, BL> bh, bl;
    wmma::load_matrix_sync(bh, bh_p, 72);
    wmma::load_matrix_sync(bl, bl_p, 72);
    wmma::mma_sync(c, ah, bh, c);
    wmma::mma_sync(c, ah, bl, c);
    wmma::mma_sync(c, al, bh, c);
}

// Warp-local: 16x16 fp32 frag -> scratch -> bf16 hi/lo region (stride 72)
__device__ __forceinline__ void conv_frag(float* scr, const FragC& cf,
                                          bf16* dh, bf16* dl, int lane) {
    wmma::store_matrix_sync(scr, cf, 20, wmma::mem_row_major);
    __syncwarp();
#pragma unroll
    for (int e = 0; e < 8; e += 2) {
        int idx = lane * 8 + e;
        int row = idx >> 4, col = idx & 15;
        float v0 = scr[row * 20 + col], v1 = scr[row * 20 + col + 1];
        bf16 h0, l0, h1, l1;
        bsplit(v0, h0, l0); bsplit(v1, h1, l1);
        *(__nv_bfloat162*)(dh + row * 72 + col) = __nv_bfloat162(h0, h1);
        *(__nv_bfloat162*)(dl + row * 72 + col) = __nv_bfloat162(l0, l1);
    }
    __syncwarp();
}

__device__ __forceinline__ void st_cluster_b32(uint32_t laddr, uint peer, uint v) {
    uint32_t raddr;
    asm("mapa.shared::cluster.u32 %0, %1, %2;" : "=r"(raddr) : "r"(laddr), "r"(peer));
    asm volatile("st.shared::cluster.b32 [%0], %1;" :: "r"(raddr), "r"(v) : "memory");
}

// xg scratch: [l][g][n][a][b]  (384 MB device .bss)
__device__ float g_xg[(size_t)3 * 128 * 64 * 64 * 64];

// ============================================================================
// Phase 1 (unchanged R10/R12 — validated): gates-parallel wmma.
// ============================================================================
#define XG_XH   0
#define XG_XL   18432
#define XG_W2H  36864
#define XG_W2L  64512
#define XG_W1H  92160
#define XG_W1L  119808
#define XG_TH   147456
#define XG_TL   175104
#define XG_SCR  202752
#define XG_SMEM 218112

__global__ void __launch_bounds__(384, 1)
xg_kernel(const float* __restrict__ inputs,
          const float* __restrict__ Ww1,
          const float* __restrict__ Ww2) {
    extern __shared__ char smx[];
    bf16* XH  = (bf16*)(smx + XG_XH);
    bf16* XL  = (bf16*)(smx + XG_XL);
    bf16* W2H = (bf16*)(smx + XG_W2H);
    bf16* W2L = (bf16*)(smx + XG_W2L);
    bf16* W1H = (bf16*)(smx + XG_W1H);
    bf16* W1L = (bf16*)(smx + XG_W1L);
    bf16* TH  = (bf16*)(smx + XG_TH);
    bf16* TL  = (bf16*)(smx + XG_TL);

    const int tid = threadIdx.x;
    const int w = tid >> 5, lane = tid & 31;
    const int g = w >> 2, mt = w & 3;
    float* scr = (float*)(smx + XG_SCR) + w * 320;

    for (int e = tid; e < 12288; e += 384) {
        int gg = e >> 12, r = (e >> 6) & 63, c = e & 63;
        bf16 h, l;
        bsplit(Ww2[e], h, l);
        W2H[gg * 4608 + r * 72 + c] = h;
        W2L[gg * 4608 + r * 72 + c] = l;
        bsplit(Ww1[e], h, l);
        W1H[gg * 4608 + r * 72 + c] = h;
        W1L[gg * 4608 + r * 72 + c] = l;
    }
    __syncthreads();

    for (int t = 0; t < 8; ++t) {
        const int flat = blockIdx.x * 8 + t;
        const int l = flat >> 6, n = flat & 63;

        const float* xsrc = inputs + ((size_t)n * 128 + l) * 4096;
        for (int e = tid; e < 4096; e += 384) {
            int i = e >> 6, j = e & 63;
            bf16 h, lo; bsplit(xsrc[e], h, lo);
            XH[i * 72 + j] = h;
            XL[i * 72 + j] = lo;
        }
        __syncthreads();

        {   // stage A
            FragC c[4];
#pragma unroll
            for (int nt = 0; nt < 4; ++nt) wmma::fill_fragment(c[nt], 0.0f);
#pragma unroll
            for (int k = 0; k < 4; ++k) {
                FragA ah, al;
                wmma::load_matrix_sync(ah, XH + mt * 16 * 72 + k * 16, 72);
                wmma::load_matrix_sync(al, XL + mt * 16 * 72 + k * 16, 72);
#pragma unroll
                for (int nt = 0; nt < 4; ++nt)
                    mma3<wmma::col_major>(c[nt], ah, al,
                        W2H + g * 4608 + nt * 16 * 72 + k * 16,
                        W2L + g * 4608 + nt * 16 * 72 + k * 16);
            }
#pragma unroll
            for (int nt = 0; nt < 4; ++nt)
                conv_frag(scr, c[nt],
                          TH + g * 4608 + mt * 16 * 72 + nt * 16,
                          TL + g * 4608 + mt * 16 * 72 + nt * 16, lane);
        }
        __syncthreads();

        {   // stage B -> global
            FragC c[4];
#pragma unroll
            for (int nt = 0; nt < 4; ++nt) wmma::fill_fragment(c[nt], 0.0f);
#pragma unroll
            for (int k = 0; k < 4; ++k) {
                FragA ah, al;
                wmma::load_matrix_sync(ah, W1H + g * 4608 + mt * 16 * 72 + k * 16, 72);
                wmma::load_matrix_sync(al, W1L + g * 4608 + mt * 16 * 72 + k * 16, 72);
#pragma unroll
                for (int nt = 0; nt < 4; ++nt)
                    mma3<wmma::row_major>(c[nt], ah, al,
                        TH + g * 4608 + k * 16 * 72 + nt * 16,
                        TL + g * 4608 + k * 16 * 72 + nt * 16);
            }
            float* dst = g_xg + ((size_t)(l * 3 + g) * 64 + n) * 4096 + mt * 16 * 64;
#pragma unroll
            for (int nt = 0; nt < 4; ++nt)
                wmma::store_matrix_sync(dst + nt * 16, c[nt], 64, wmma::mem_row_major);
        }
        __syncthreads();
    }
}

// ============================================================================
// Phase 2: cluster-2 wmma recurrence. 128 CTAs x 192 threads.
// Rank owns a-rows [32r, 32r+32). Ping-pong h (full 64 rows per CTA, peer
// half delivered via DSMEM). Per step: prefetch xg frags -> stage1 (6 warps,
// own tmp rows) -> CTA sync -> stage2+elementwise (4 warps) -> cluster barrier.
// ============================================================================
// byte offsets (bf16 arrays sized in bytes)
#define RC_HB0H  0         // [64][72] bf16 = 9216
#define RC_HB0L  9216
#define RC_HB1H  18432
#define RC_HB1L  27648
#define RC_W1H   36864     // [3][32][72] = 13824
#define RC_W1L   50688
#define RC_W2H   64512     // [3][64][72] = 27648
#define RC_W2L   92160
#define RC_TH    119808    // [3][32][72] = 13824
#define RC_TL    133632
#define RC_SCR   147456    // 6 warps x 320 fp32
#define RC_SMEM  155136

__global__ void __launch_bounds__(192, 1) __cluster_dims__(2, 1, 1)
rec_kernel(const float* __restrict__ Wu1,
           const float* __restrict__ Wu2,
           float* __restrict__ out) {
    extern __shared__ char smx[];
    bf16* W1H = (bf16*)(smx + RC_W1H);
    bf16* W1L = (bf16*)(smx + RC_W1L);
    bf16* W2H = (bf16*)(smx + RC_W2H);
    bf16* W2L = (bf16*)(smx + RC_W2L);
    bf16* TH  = (bf16*)(smx + RC_TH);
    bf16* TL  = (bf16*)(smx + RC_TL);

    const int bid  = blockIdx.x;
    const int n    = bid >> 1;
    const int rank = bid & 1;
    const int tid  = threadIdx.x;
    const int w = tid >> 5, lane = tid & 31;
    const int g1 = w >> 1, mt1 = w & 1;      // stage1 role (6 warps)
    const int mt2 = w >> 1, nh2 = w & 1;     // stage2 role (w < 4)
    float* scrw = (float*)(smx + RC_SCR) + w * 320;

    uint32_t sbase;
    asm("{ .reg .u64 t; cvta.to.shared.u64 t, %1; cvt.u32.u64 %0, t; }"
        : "=r"(sbase) : "l"(smx));
    const uint peer = rank ^ 1;

    // weights: W1 = own 32 a-rows; W2 = full
    for (int e = tid; e < 6144; e += 192) {           // 3*32*64
        int gg = e >> 11, al = (e >> 6) & 31, i = e & 63;
        bf16 h, l;
        bsplit(Wu1[gg * 4096 + (32 * rank + al) * 64 + i], h, l);
        W1H[gg * 2304 + al * 72 + i] = h;
        W1L[gg * 2304 + al * 72 + i] = l;
    }
    for (int e = tid; e < 12288; e += 192) {          // 3*64*64
        int gg = e >> 12, b = (e >> 6) & 63, j = e & 63;
        bf16 h, l;
        bsplit(Wu2[gg * 4096 + b * 64 + j], h, l);
        W2H[gg * 4608 + b * 72 + j] = h;
        W2L[gg * 4608 + b * 72 + j] = l;
    }
    for (int e = tid; e < 18432; e += 192)            // both h ping-pong buffers
        ((bf16*)smx)[e] = __float2bfloat16(0.f);

    float cst[16];
#pragma unroll
    for (int e = 0; e < 16; ++e) cst[e] = 0.f;

    __syncthreads();
    asm volatile("barrier.cluster.arrive.aligned;" ::: "memory");
    asm volatile("barrier.cluster.wait.aligned;"   ::: "memory");

    for (int l = 0; l < 128; ++l) {
        bf16* hTH = (bf16*)(smx + ((l & 1) ? RC_HB1H : RC_HB0H));
        bf16* hTL = (bf16*)(smx + ((l & 1) ? RC_HB1L : RC_HB0L));
        const int hNoffH = (l & 1) ? RC_HB0H : RC_HB1H;
        const int hNoffL = (l & 1) ? RC_HB0L : RC_HB1L;
        bf16* hNH = (bf16*)(smx + hNoffH);
        bf16* hNL = (bf16*)(smx + hNoffL);

        // ---- prefetch xg accumulators (stage2 warps; hidden behind stage1) ----
        FragC c[3][2];
        if (w < 4) {
#pragma unroll
            for (int gg = 0; gg < 3; ++gg)
#pragma unroll
                for (int nt = 0; nt < 2; ++nt)
                    wmma::load_matrix_sync(c[gg][nt],
                        g_xg + ((size_t)(l * 3 + gg) * 64 + n) * 4096
                             + (size_t)(32 * rank + mt2 * 16) * 64
                             + (nh2 * 2 + nt) * 16,
                        64, wmma::mem_row_major);
        }

        // ---- stage1: warp (g1, mt1): own tmp rows 16*mt1, cols 0..63 ----
        {
            FragC c1[4];
#pragma unroll
            for (int nt = 0; nt < 4; ++nt) wmma::fill_fragment(c1[nt], 0.0f);
#pragma unroll
            for (int k = 0; k < 4; ++k) {
                FragA ah, al;
                wmma::load_matrix_sync(ah, W1H + g1 * 2304 + mt1 * 16 * 72 + k * 16, 72);
                wmma::load_matrix_sync(al, W1L + g1 * 2304 + mt1 * 16 * 72 + k * 16, 72);
#pragma unroll
                for (int nt = 0; nt < 4; ++nt)
                    mma3<wmma::row_major>(c1[nt], ah, al,
                        hTH + k * 16 * 72 + nt * 16,
                        hTL + k * 16 * 72 + nt * 16);
            }
#pragma unroll
            for (int nt = 0; nt < 4; ++nt)
                conv_frag(scrw, c1[nt],
                          TH + g1 * 2304 + mt1 * 16 * 72 + nt * 16,
                          TL + g1 * 2304 + mt1 * 16 * 72 + nt * 16, lane);
        }
        __syncthreads();

        // ---- stage2 + elementwise: warps 0..3 ----
        if (w < 4) {
#pragma unroll
            for (int gg = 0; gg < 3; ++gg) {
#pragma unroll
                for (int k = 0; k < 4; ++k) {
                    FragA ah, al;
                    wmma::load_matrix_sync(ah, TH + gg * 2304 + mt2 * 16 * 72 + k * 16, 72);
                    wmma::load_matrix_sync(al, TL + gg * 2304 + mt2 * 16 * 72 + k * 16, 72);
#pragma unroll
                    for (int nt = 0; nt < 2; ++nt) {
                        int ntg = nh2 * 2 + nt;
                        mma3<wmma::col_major>(c[gg][nt], ah, al,
                            W2H + gg * 4608 + ntg * 16 * 72 + k * 16,
                            W2L + gg * 4608 + ntg * 16 * 72 + k * 16);
                    }
                }
            }
            float* orow = out + ((size_t)n * 128 + l) * 4096;
#pragma unroll
            for (int nt = 0; nt < 2; ++nt) {
#pragma unroll
                for (int i = 0; i < 8; ++i) {
                    float z = sigmoidf(c[0][nt].x[i]);
                    float r = sigmoidf(c[1][nt].x[i]);
                    float o = sigmoidf(c[2][nt].x[i]);
                    int ci = nt * 8 + i;
                    float cn = r * (cst[ci] + z);   // c = r*c + z*r
                    cst[ci] = cn;
                    c[0][nt].x[i] = o * sigmoidf(cn);  // h
                }
                wmma::store_matrix_sync(scrw, c[0][nt], 20, wmma::mem_row_major);
                __syncwarp();
#pragma unroll
                for (int e = 0; e < 8; e += 2) {
                    int idx = lane * 8 + e;
                    int row = idx >> 4, col = idx & 15;
                    int ag = 32 * rank + mt2 * 16 + row;     // global a
                    int b = (nh2 * 2 + nt) * 16 + col;
                    float v0 = scrw[row * 20 + col], v1 = scrw[row * 20 + col + 1];
                    *(float2*)(orow + ag * 64 + b) = make_float2(v0, v1);
                    bf16 h0, l0, h1, l1;
                    bsplit(v0, h0, l0); bsplit(v1, h1, l1);
                    __nv_bfloat162 hw = __nv_bfloat162(h0, h1);
                    __nv_bfloat162 lw = __nv_bfloat162(l0, l1);
                    *(__nv_bfloat162*)(hNH + ag * 72 + b) = hw;
                    *(__nv_bfloat162*)(hNL + ag * 72 + b) = lw;
                    uint off = (uint)(ag * 72 + b) * 2;
                    st_cluster_b32(sbase + hNoffH + off, peer,
                                   *(uint*)&hw);
                    st_cluster_b32(sbase + hNoffL + off, peer,
                                   *(uint*)&lw);
                }
                __syncwarp();
            }
        }
        asm volatile("barrier.cluster.arrive.aligned;" ::: "memory");
        asm volatile("barrier.cluster.wait.aligned;"   ::: "memory");
    }

    // epilogue: h_last = own half of outs[:,127]; c_last from registers
    {
        const float* hsrc = out + ((size_t)n * 128 + 127) * 4096 + rank * 2048;
        float* hl = out + 33554432ull + (size_t)n * 4096 + rank * 2048;
        for (int e = tid; e < 2048; e += 192) hl[e] = hsrc[e];
        if (w < 4) {
            float* cl = out + 33816576ull + (size_t)n * 4096;
#pragma unroll
            for (int nt = 0; nt < 2; ++nt) {
                FragC cf;
#pragma unroll
                for (int i = 0; i < 8; ++i) cf.x[i] = cst[nt * 8 + i];
                wmma::store_matrix_sync(scrw, cf, 20, wmma::mem_row_major);
                __syncwarp();
#pragma unroll
                for (int e = 0; e < 8; e += 2) {
                    int idx = lane * 8 + e;
                    int row = idx >> 4, col = idx & 15;
                    int ag = 32 * rank + mt2 * 16 + row;
                    int b = (nh2 * 2 + nt) * 16 + col;
                    *(float2*)(cl + ag * 64 + b) =
                        make_float2(scrw[row * 20 + col], scrw[row * 20 + col + 1]);
                }
                __syncwarp();
            }
        }
    }
}

// ============================================================================
extern "C" void kernel_launch(void* const* d_in, const int* in_sizes, int n_in,
                              void* d_out, int out_size) {
    const float* inputs = (const float*)d_in[0];   // (64,128,64,64)
    const float* Ww1    = (const float*)d_in[1];   // (4,64,64) — g<3 used
    const float* Ww2    = (const float*)d_in[2];
    const float* Wu1    = (const float*)d_in[3];
    const float* Wu2    = (const float*)d_in[4];
    float* out = (float*)d_out;

    cudaFuncSetAttribute(xg_kernel,  cudaFuncAttributeMaxDynamicSharedMemorySize, XG_SMEM);
    cudaFuncSetAttribute(rec_kernel, cudaFuncAttributeMaxDynamicSharedMemorySize, RC_SMEM);

    xg_kernel<<<1024, 384, XG_SMEM>>>(inputs, Ww1, Ww2);
    rec_kernel<<<128, 192, RC_SMEM>>>(Wu1, Wu2, out);
}

// round 14
// speedup vs baseline: 2.0478x; 1.1706x over previous
#include <cuda_runtime.h>
#include <cuda_bf16.h>
#include <mma.h>
#include <cstdint>

using namespace nvcuda;
typedef __nv_bfloat16 bf16;
typedef unsigned int uint;

__device__ __forceinline__ float sigmoidf(float x) {
    return __fdividef(1.0f, 1.0f + __expf(-x));
}
// bf16 hi/lo split: v = h + l + O(2^-18 v)
__device__ __forceinline__ void bsplit(float v, bf16& h, bf16& l) {
    h = __float2bfloat16(v);
    l = __float2bfloat16(v - __bfloat162float(h));
}

typedef wmma::fragment<wmma::accumulator, 16, 16, 16, float> FragC;
typedef wmma::fragment<wmma::matrix_a, 16, 16, 16, bf16, wmma::row_major> FragA;

// Warp-local: 16x16 fp32 frag -> scratch -> bf16 hi/lo region (stride 72)
__device__ __forceinline__ void conv_frag(float* scr, const FragC& cf,
                                          bf16* dh, bf16* dl, int lane) {
    wmma::store_matrix_sync(scr, cf, 20, wmma::mem_row_major);
    __syncwarp();
#pragma unroll
    for (int e = 0; e < 8; e += 2) {
        int idx = lane * 8 + e;
        int row = idx >> 4, col = idx & 15;
        float v0 = scr[row * 20 + col], v1 = scr[row * 20 + col + 1];
        bf16 h0, l0, h1, l1;
        bsplit(v0, h0, l0); bsplit(v1, h1, l1);
        *(__nv_bfloat162*)(dh + row * 72 + col) = __nv_bfloat162(h0, h1);
        *(__nv_bfloat162*)(dl + row * 72 + col) = __nv_bfloat162(l0, l1);
    }
    __syncwarp();
}

__device__ __forceinline__ void sum3(FragC& d, const FragC s[3]) {
#pragma unroll
    for (int i = 0; i < d.num_elements; ++i)
        d.x[i] = s[0].x[i] + s[1].x[i] + s[2].x[i];
}

__device__ __forceinline__ void st_cluster_b32(uint32_t laddr, uint peer, uint v) {
    uint32_t raddr;
    asm("mapa.shared::cluster.u32 %0, %1, %2;" : "=r"(raddr) : "r"(laddr), "r"(peer));
    asm volatile("st.shared::cluster.b32 [%0], %1;" :: "r"(raddr), "r"(v) : "memory");
}

// xg scratch: [l][g][n][a][b]  (384 MB device .bss)
__device__ float g_xg[(size_t)3 * 128 * 64 * 64 * 64];

// ============================================================================
// Phase 1: gates-parallel wmma, split-term accumulators (chains 4-deep).
// ============================================================================
#define XG_XH   0
#define XG_XL   18432
#define XG_W2H  36864
#define XG_W2L  64512
#define XG_W1H  92160
#define XG_W1L  119808
#define XG_TH   147456
#define XG_TL   175104
#define XG_SCR  202752
#define XG_SMEM 218112

__global__ void __launch_bounds__(384, 1)
xg_kernel(const float* __restrict__ inputs,
          const float* __restrict__ Ww1,
          const float* __restrict__ Ww2) {
    extern __shared__ char smx[];
    bf16* XH  = (bf16*)(smx + XG_XH);
    bf16* XL  = (bf16*)(smx + XG_XL);
    bf16* W2H = (bf16*)(smx + XG_W2H);
    bf16* W2L = (bf16*)(smx + XG_W2L);
    bf16* W1H = (bf16*)(smx + XG_W1H);
    bf16* W1L = (bf16*)(smx + XG_W1L);
    bf16* TH  = (bf16*)(smx + XG_TH);
    bf16* TL  = (bf16*)(smx + XG_TL);

    const int tid = threadIdx.x;
    const int w = tid >> 5, lane = tid & 31;
    const int g = w >> 2, mt = w & 3;
    float* scr = (float*)(smx + XG_SCR) + w * 320;

    for (int e = tid; e < 12288; e += 384) {
        int gg = e >> 12, r = (e >> 6) & 63, c = e & 63;
        bf16 h, l;
        bsplit(Ww2[e], h, l);
        W2H[gg * 4608 + r * 72 + c] = h;
        W2L[gg * 4608 + r * 72 + c] = l;
        bsplit(Ww1[e], h, l);
        W1H[gg * 4608 + r * 72 + c] = h;
        W1L[gg * 4608 + r * 72 + c] = l;
    }
    __syncthreads();

    for (int t = 0; t < 8; ++t) {
        const int flat = blockIdx.x * 8 + t;
        const int l = flat >> 6, n = flat & 63;

        const float* xsrc = inputs + ((size_t)n * 128 + l) * 4096;
        for (int e = tid; e < 4096; e += 384) {
            int i = e >> 6, j = e & 63;
            bf16 h, lo; bsplit(xsrc[e], h, lo);
            XH[i * 72 + j] = h;
            XL[i * 72 + j] = lo;
        }
        __syncthreads();

        // stage A: T_g[i,b], two passes of 2 nt; per acc chain = 4
        for (int half = 0; half < 2; ++half) {
            FragC s[2][3];
#pragma unroll
            for (int nt = 0; nt < 2; ++nt)
#pragma unroll
                for (int tm = 0; tm < 3; ++tm) wmma::fill_fragment(s[nt][tm], 0.0f);
#pragma unroll
            for (int k = 0; k < 4; ++k) {
                FragA ah, al;
                wmma::load_matrix_sync(ah, XH + mt * 16 * 72 + k * 16, 72);
                wmma::load_matrix_sync(al, XL + mt * 16 * 72 + k * 16, 72);
#pragma unroll
                for (int nt = 0; nt < 2; ++nt) {
                    int ntg = half * 2 + nt;
                    wmma::fragment<wmma::matrix_b, 16, 16, 16, bf16, wmma::col_major> bh, bl;
                    wmma::load_matrix_sync(bh, W2H + g * 4608 + ntg * 16 * 72 + k * 16, 72);
                    wmma::load_matrix_sync(bl, W2L + g * 4608 + ntg * 16 * 72 + k * 16, 72);
                    wmma::mma_sync(s[nt][0], ah, bh, s[nt][0]);
                    wmma::mma_sync(s[nt][1], ah, bl, s[nt][1]);
                    wmma::mma_sync(s[nt][2], al, bh, s[nt][2]);
                }
            }
#pragma unroll
            for (int nt = 0; nt < 2; ++nt) {
                FragC d; sum3(d, s[nt]);
                int ntg = half * 2 + nt;
                conv_frag(scr, d,
                          TH + g * 4608 + mt * 16 * 72 + ntg * 16,
                          TL + g * 4608 + mt * 16 * 72 + ntg * 16, lane);
            }
        }
        __syncthreads();

        // stage B -> global
        for (int half = 0; half < 2; ++half) {
            FragC s[2][3];
#pragma unroll
            for (int nt = 0; nt < 2; ++nt)
#pragma unroll
                for (int tm = 0; tm < 3; ++tm) wmma::fill_fragment(s[nt][tm], 0.0f);
#pragma unroll
            for (int k = 0; k < 4; ++k) {
                FragA ah, al;
                wmma::load_matrix_sync(ah, W1H + g * 4608 + mt * 16 * 72 + k * 16, 72);
                wmma::load_matrix_sync(al, W1L + g * 4608 + mt * 16 * 72 + k * 16, 72);
#pragma unroll
                for (int nt = 0; nt < 2; ++nt) {
                    int ntg = half * 2 + nt;
                    wmma::fragment<wmma::matrix_b, 16, 16, 16, bf16, wmma::row_major> bh, bl;
                    wmma::load_matrix_sync(bh, TH + g * 4608 + k * 16 * 72 + ntg * 16, 72);
                    wmma::load_matrix_sync(bl, TL + g * 4608 + k * 16 * 72 + ntg * 16, 72);
                    wmma::mma_sync(s[nt][0], ah, bh, s[nt][0]);
                    wmma::mma_sync(s[nt][1], ah, bl, s[nt][1]);
                    wmma::mma_sync(s[nt][2], al, bh, s[nt][2]);
                }
            }
            float* dst = g_xg + ((size_t)(l * 3 + g) * 64 + n) * 4096 + mt * 16 * 64;
#pragma unroll
            for (int nt = 0; nt < 2; ++nt) {
                FragC d; sum3(d, s[nt]);
                wmma::store_matrix_sync(dst + (half * 2 + nt) * 16, d, 64,
                                        wmma::mem_row_major);
            }
        }
        __syncthreads();
    }
}

// ============================================================================
// Phase 2: cluster-2, 384 threads (12 warps), split-term accumulators,
// scalar elementwise via fp32 gbuf. 2 CTA syncs + 1 cluster barrier per step.
// ============================================================================
#define RC_HB0H  0          // [64][72] bf16
#define RC_HB0L  9216
#define RC_HB1H  18432
#define RC_HB1L  27648
#define RC_W1H   36864      // [3][32][72] bf16
#define RC_W1L   50688
#define RC_W2H   64512      // [3][64][72] bf16
#define RC_W2L   92160
#define RC_TH    119808     // [3][32][72] bf16
#define RC_TL    133632
#define RC_GB    147456     // [3][32][68] fp32 = 26112
#define RC_SCR   173568     // 12 x 320 fp32
#define RC_SMEM  188928

__global__ void __launch_bounds__(384, 1) __cluster_dims__(2, 1, 1)
rec_kernel(const float* __restrict__ Wu1,
           const float* __restrict__ Wu2,
           float* __restrict__ out) {
    extern __shared__ char smx[];
    bf16* W1H = (bf16*)(smx + RC_W1H);
    bf16* W1L = (bf16*)(smx + RC_W1L);
    bf16* W2H = (bf16*)(smx + RC_W2H);
    bf16* W2L = (bf16*)(smx + RC_W2L);
    bf16* TH  = (bf16*)(smx + RC_TH);
    bf16* TL  = (bf16*)(smx + RC_TL);
    float* GB = (float*)(smx + RC_GB);

    const int bid  = blockIdx.x;
    const int n    = bid >> 1;
    const int rank = bid & 1;
    const int tid  = threadIdx.x;
    const int w = tid >> 5, lane = tid & 31;
    // 12 warp tasks both stages: (g, mt in {0,1}, half in {0,1})
    const int gw = w >> 2, mtw = (w >> 1) & 1, hw = w & 1;
    float* scrw = (float*)(smx + RC_SCR) + w * 320;

    uint32_t sbase;
    asm("{ .reg .u64 t; cvta.to.shared.u64 t, %1; cvt.u32.u64 %0, t; }"
        : "=r"(sbase) : "l"(smx));
    const uint peer = rank ^ 1;

    // weights: W1 = own 32 a-rows; W2 = full
    for (int e = tid; e < 6144; e += 384) {
        int gg = e >> 11, al = (e >> 6) & 31, i = e & 63;
        bf16 h, l;
        bsplit(Wu1[gg * 4096 + (32 * rank + al) * 64 + i], h, l);
        W1H[gg * 2304 + al * 72 + i] = h;
        W1L[gg * 2304 + al * 72 + i] = l;
    }
    for (int e = tid; e < 12288; e += 384) {
        int gg = e >> 12, b = (e >> 6) & 63, j = e & 63;
        bf16 h, l;
        bsplit(Wu2[gg * 4096 + b * 64 + j], h, l);
        W2H[gg * 4608 + b * 72 + j] = h;
        W2L[gg * 4608 + b * 72 + j] = l;
    }
    for (int e = tid; e < 18432; e += 384)   // zero both h ping-pong buffers
        ((bf16*)smx)[e] = __float2bfloat16(0.f);

    float cst[6];
#pragma unroll
    for (int e = 0; e < 6; ++e) cst[e] = 0.f;

    __syncthreads();
    asm volatile("barrier.cluster.arrive.aligned;" ::: "memory");
    asm volatile("barrier.cluster.wait.aligned;"   ::: "memory");

    for (int l = 0; l < 128; ++l) {
        bf16* hTH = (bf16*)(smx + ((l & 1) ? RC_HB1H : RC_HB0H));
        bf16* hTL = (bf16*)(smx + ((l & 1) ? RC_HB1L : RC_HB0L));
        const int hNoffH = (l & 1) ? RC_HB0H : RC_HB1H;
        const int hNoffL = (l & 1) ? RC_HB0L : RC_HB1L;
        bf16* hNH = (bf16*)(smx + hNoffH);
        bf16* hNL = (bf16*)(smx + hNoffL);

        // ---- stage1: warp (gw, mtw, hw): tmp rows 16*mtw, cols 32*hw ----
        {
            FragC s[2][3];
#pragma unroll
            for (int nt = 0; nt < 2; ++nt)
#pragma unroll
                for (int tm = 0; tm < 3; ++tm) wmma::fill_fragment(s[nt][tm], 0.0f);
#pragma unroll
            for (int k = 0; k < 4; ++k) {
                FragA ah, al;
                wmma::load_matrix_sync(ah, W1H + gw * 2304 + mtw * 16 * 72 + k * 16, 72);
                wmma::load_matrix_sync(al, W1L + gw * 2304 + mtw * 16 * 72 + k * 16, 72);
#pragma unroll
                for (int nt = 0; nt < 2; ++nt) {
                    int ntg = hw * 2 + nt;
                    wmma::fragment<wmma::matrix_b, 16, 16, 16, bf16, wmma::row_major> bh, bl;
                    wmma::load_matrix_sync(bh, hTH + k * 16 * 72 + ntg * 16, 72);
                    wmma::load_matrix_sync(bl, hTL + k * 16 * 72 + ntg * 16, 72);
                    wmma::mma_sync(s[nt][0], ah, bh, s[nt][0]);
                    wmma::mma_sync(s[nt][1], ah, bl, s[nt][1]);
                    wmma::mma_sync(s[nt][2], al, bh, s[nt][2]);
                }
            }
#pragma unroll
            for (int nt = 0; nt < 2; ++nt) {
                FragC d; sum3(d, s[nt]);
                int ntg = hw * 2 + nt;
                conv_frag(scrw, d,
                          TH + gw * 2304 + mtw * 16 * 72 + ntg * 16,
                          TL + gw * 2304 + mtw * 16 * 72 + ntg * 16, lane);
            }
        }
        __syncthreads();

        // xg prefetch (coalesced float2; hidden behind stage2 mma stream)
        float2 xg2[3][3];
#pragma unroll
        for (int idx = 0; idx < 3; ++idx) {
            int p = tid + idx * 384;
            if (p < 1024) {
                int e = 2 * p, row = e >> 6, col = e & 63;
                int ag = 32 * rank + row;
#pragma unroll
                for (int gg = 0; gg < 3; ++gg)
                    xg2[gg][idx] = *(const float2*)(g_xg +
                        ((size_t)(l * 3 + gg) * 64 + n) * 4096 + ag * 64 + col);
            }
        }

        // ---- stage2: warp (gw, mtw, hw): hg rows 16*mtw, cols 32*hw -> GB ----
        {
            FragC s[2][3];
#pragma unroll
            for (int nt = 0; nt < 2; ++nt)
#pragma unroll
                for (int tm = 0; tm < 3; ++tm) wmma::fill_fragment(s[nt][tm], 0.0f);
#pragma unroll
            for (int k = 0; k < 4; ++k) {
                FragA ah, al;
                wmma::load_matrix_sync(ah, TH + gw * 2304 + mtw * 16 * 72 + k * 16, 72);
                wmma::load_matrix_sync(al, TL + gw * 2304 + mtw * 16 * 72 + k * 16, 72);
#pragma unroll
                for (int nt = 0; nt < 2; ++nt) {
                    int ntg = hw * 2 + nt;
                    wmma::fragment<wmma::matrix_b, 16, 16, 16, bf16, wmma::col_major> bh, bl;
                    wmma::load_matrix_sync(bh, W2H + gw * 4608 + ntg * 16 * 72 + k * 16, 72);
                    wmma::load_matrix_sync(bl, W2L + gw * 4608 + ntg * 16 * 72 + k * 16, 72);
                    wmma::mma_sync(s[nt][0], ah, bh, s[nt][0]);
                    wmma::mma_sync(s[nt][1], ah, bl, s[nt][1]);
                    wmma::mma_sync(s[nt][2], al, bh, s[nt][2]);
                }
            }
#pragma unroll
            for (int nt = 0; nt < 2; ++nt) {
                FragC d; sum3(d, s[nt]);
                wmma::store_matrix_sync(
                    GB + gw * 2176 + mtw * 16 * 68 + (hw * 2 + nt) * 16,
                    d, 68, wmma::mem_row_major);
            }
        }
        __syncthreads();

        // ---- elementwise: all 384 threads, pairs ----
        {
            float* orow = out + ((size_t)n * 128 + l) * 4096;
#pragma unroll
            for (int idx = 0; idx < 3; ++idx) {
                int p = tid + idx * 384;
                if (p < 1024) {
                    int e = 2 * p, row = e >> 6, col = e & 63;
                    int ag = 32 * rank + row;
                    const float* gb = GB + row * 68 + col;
                    float z0 = sigmoidf(gb[0]        + xg2[0][idx].x);
                    float z1 = sigmoidf(gb[1]        + xg2[0][idx].y);
                    float r0 = sigmoidf(gb[2176]     + xg2[1][idx].x);
                    float r1 = sigmoidf(gb[2177]     + xg2[1][idx].y);
                    float o0 = sigmoidf(gb[4352]     + xg2[2][idx].x);
                    float o1 = sigmoidf(gb[4353]     + xg2[2][idx].y);
                    float c0 = r0 * (cst[2*idx]   + z0);
                    float c1 = r1 * (cst[2*idx+1] + z1);
                    cst[2*idx] = c0; cst[2*idx+1] = c1;
                    float h0 = o0 * sigmoidf(c0);
                    float h1 = o1 * sigmoidf(c1);
                    *(float2*)(orow + ag * 64 + col) = make_float2(h0, h1);
                    bf16 hh0, hl0, hh1, hl1;
                    bsplit(h0, hh0, hl0); bsplit(h1, hh1, hl1);
                    __nv_bfloat162 hw2 = __nv_bfloat162(hh0, hh1);
                    __nv_bfloat162 lw2 = __nv_bfloat162(hl0, hl1);
                    uint off = (uint)(ag * 72 + col) * 2;
                    *(__nv_bfloat162*)(hNH + ag * 72 + col) = hw2;
                    *(__nv_bfloat162*)(hNL + ag * 72 + col) = lw2;
                    st_cluster_b32(sbase + hNoffH + off, peer, *(uint*)&hw2);
                    st_cluster_b32(sbase + hNoffL + off, peer, *(uint*)&lw2);
                }
            }
        }
        asm volatile("barrier.cluster.arrive.aligned;" ::: "memory");
        asm volatile("barrier.cluster.wait.aligned;"   ::: "memory");
    }

    // epilogue: h_last = own half of outs[:,127]; c_last from cst
    {
        const float* hsrc = out + ((size_t)n * 128 + 127) * 4096 + rank * 2048;
        float* hl = out + 33554432ull + (size_t)n * 4096 + rank * 2048;
        for (int e = tid; e < 2048; e += 384) hl[e] = hsrc[e];
        float* cl = out + 33816576ull + (size_t)n * 4096;
#pragma unroll
        for (int idx = 0; idx < 3; ++idx) {
            int p = tid + idx * 384;
            if (p < 1024) {
                int e = 2 * p, row = e >> 6, col = e & 63;
                int ag = 32 * rank + row;
                *(float2*)(cl + ag * 64 + col) =
                    make_float2(cst[2*idx], cst[2*idx+1]);
            }
        }
    }
}

// ============================================================================
extern "C" void kernel_launch(void* const* d_in, const int* in_sizes, int n_in,
                              void* d_out, int out_size) {
    const float* inputs = (const float*)d_in[0];   // (64,128,64,64)
    const float* Ww1    = (const float*)d_in[1];   // (4,64,64) — g<3 used
    const float* Ww2    = (const float*)d_in[2];
    const float* Wu1    = (const float*)d_in[3];
    const float* Wu2    = (const float*)d_in[4];
    float* out = (float*)d_out;

    cudaFuncSetAttribute(xg_kernel,  cudaFuncAttributeMaxDynamicSharedMemorySize, XG_SMEM);
    cudaFuncSetAttribute(rec_kernel, cudaFuncAttributeMaxDynamicSharedMemorySize, RC_SMEM);

    xg_kernel<<<1024, 384, XG_SMEM>>>(inputs, Ww1, Ww2);
    rec_kernel<<<128, 384, RC_SMEM>>>(Wu1, Wu2, out);
}